// round 10
// baseline (speedup 1.0000x reference)
#include <cuda_runtime.h>
#include <cuda_bf16.h>

// Problem constants (fixed by reference)
#define IN_DIM   128
#define OUT_DIM  128
#define NCP      11
#define SSTR     18     // slots per i: 0..2 zero, 3..13 = sf*cp[0..10], 14..17 zero
#define OCH      32     // o per CTA
#define TB       32     // batch rows per CTA (= warps per CTA)
#define NTH      1024

// smem layout (bytes)
#define TS_BYTES  (IN_DIM * SSTR * OCH * 2)   // 147456 (bf16 table, all i, 32 o)
#define SFS_OFF   TS_BYTES
#define SFS_BYTES (IN_DIM * OCH * 4)          // 16384 (fp32 sf)
#define W4S_OFF   (SFS_OFF + SFS_BYTES)       // 163840
#define W4S_BYTES (TB * IN_DIM * 16)          // 65536 (weights; aliased as cp staging)
#define SMEM_TOT  (W4S_OFF + W4S_BYTES)       // 229376  (< 232448 cap)

typedef unsigned long long u64t;

__device__ __forceinline__ void fma2(u64t& d, u64t a, u64t b) {
    asm("fma.rn.f32x2 %0, %1, %2, %0;" : "+l"(d) : "l"(a), "l"(b));
}
__device__ __forceinline__ u64t add2(u64t a, u64t b) {
    u64t d; asm("add.rn.f32x2 %0, %1, %2;" : "=l"(d) : "l"(a), "l"(b)); return d;
}
__device__ __forceinline__ u64t pack2(float x, float y) {
    u64t p; asm("mov.b64 %0, {%1, %2};" : "=l"(p) : "f"(x), "f"(y)); return p;
}
__device__ __forceinline__ float2 unpack2(u64t p) {
    float2 r; asm("mov.b64 {%0, %1}, %2;" : "=f"(r.x), "=f"(r.y) : "l"(p)); return r;
}
// bf16x2 word -> f32x2 pair (2x PRMT)
__device__ __forceinline__ u64t bfpair(unsigned u) {
    unsigned lo = __byte_perm(u, 0, 0x1044);
    unsigned hi = __byte_perm(u, 0, 0x3244);
    u64t p; asm("mov.b64 %0, {%1, %2};" : "=l"(p) : "r"(lo), "r"(hi)); return p;
}

__global__ __launch_bounds__(NTH, 1)
void kan_fused(const float* __restrict__ x, const float* __restrict__ cp,
               const float* __restrict__ sf, float* __restrict__ out, int batch) {
    extern __shared__ char smem[];
    __nv_bfloat16* Ts  = (__nv_bfloat16*)smem;              // [128i][18s][32o] bf16
    float*         sfs = (float*)(smem + SFS_OFF);          // [128i][32o] fp32
    float4*        w4s = (float4*)(smem + W4S_OFF);         // [32b][128i] weight sets
    float*         cps = (float*)(smem + W4S_OFF);          // staging alias (pre-weights)

    const int tid   = threadIdx.x;
    const int b0    = blockIdx.x * TB;
    const int obase = blockIdx.y * OCH;

    // ---- early x preload for weight sets (hides LDG latency behind build) ----
    float xv[4];
#pragma unroll
    for (int k = 0; k < 4; k++) {
        int s = tid + k * NTH;          // s = b*128 + i
        int b = s >> 7, i = s & 127;
        xv[k] = (b0 + b < batch) ? x[(size_t)(b0 + b) * IN_DIM + i] : 0.0f;
    }

    // ---- stage sf chunk [128i][32o] fp32 (coalesced) ----
    {
        int i = tid >> 3, q = tid & 7;
        ((float4*)sfs)[tid] = ((const float4*)sf)[i * (IN_DIM / 4) + (obase / 4) + q];
    }
    // ---- zero table (pad slots must be 0; data slots overwritten later) ----
    {
        uint4 z = make_uint4(0u, 0u, 0u, 0u);
        uint4* d = (uint4*)Ts;
#pragma unroll
        for (int k = 0; k < TS_BYTES / 16 / NTH; k++) d[tid + k * NTH] = z;  // 9
    }
    __syncthreads();

    // ---- build table: 4 rounds of (stage 32-i cp slice -> scatter to bf16) ----
#pragma unroll 1
    for (int r = 0; r < 4; r++) {
        const int iB = r * 32;
        // stage cp[iB..iB+32)[obase..obase+32)[11] = 2816 float4, coalesced
        const float4* cp4 = (const float4*)cp;   // 352 float4 per i-row
#pragma unroll
        for (int k = 0; k < 3; k++) {
            int idx = tid + k * NTH;
            if (idx < 2816) {
                int iL = idx / 88, rem = idx - iL * 88;   // 88 float4 per (i, 32o) slice
                ((float4*)cps)[idx] =
                    cp4[(size_t)(iB + iL) * 352 + (obase / 4) * 11 + rem];
            }
        }
        __syncthreads();
        // scatter: 11264 elements, warp = 32 consecutive o of one (i,m)
        // LDS stride 11 words (gcd(11,32)=1: conflict-free); STS 64B contiguous
#pragma unroll
        for (int k = 0; k < 11; k++) {
            int e  = tid + k * NTH;
            int iL = e / 352, rem = e - iL * 352;
            int m  = rem >> 5, o = rem & 31;
            float v  = cps[(iL * 32 + o) * NCP + m];
            float sv = sfs[(iB + iL) * OCH + o];
            Ts[((iB + iL) * SSTR + m + 3) * OCH + o] = __float2bfloat16(sv * v);
        }
        __syncthreads();
    }

    // ---- weights: (w0,w2,w3, silu|j) per (b,i); w1 = 1-w0-w2-w3 ----
#pragma unroll
    for (int k = 0; k < 4; k++) {
        int s = tid + k * NTH;
        float xx  = xv[k];
        float pos = (xx + 1.75f) * 4.0f;
        float fj  = floorf(pos);
        int   jj  = (int)fj;
        float w0 = 1.0f, w2 = 0.0f, w3 = 0.0f;
        int j = 14;  // all-zero window for out-of-range x
        if (jj >= 0 && jj <= 13) {
            float u = pos - fj, u2 = u * u, u3 = u2 * u, vv = 1.0f - u;
            const float c = 1.0f / 6.0f;
            w0 = vv * vv * vv * c;
            w2 = (-3.0f * u3 + 3.0f * u2 + 3.0f * u + 1.0f) * c;
            w3 = u3 * c;
            j  = jj;
        }
        float sil = xx / (1.0f + __expf(-xx));
        unsigned su = (__float_as_uint(sil) & ~15u) | (unsigned)j;
        w4s[s] = make_float4(w0, w2, w3, __uint_as_float(su));
    }
    __syncthreads();

    // ---- main loop: warp = one b row; lane = (ih 0..7, oq 0..3) ----
    const int warp = tid >> 5, lane = tid & 31;
    const int ih = lane >> 2, oq = lane & 3;
    if (b0 + warp >= batch) return;   // no further CTA-wide syncs

    u64t acc01 = 0, acc23 = 0, acc45 = 0, acc67 = 0;
    const float4*     wq  = w4s + (warp << 7) + (ih << 4);
    const ulonglong2* sf2 = (const ulonglong2*)sfs;
    const uint4*      Tu  = (const uint4*)Ts;   // 4 uint4 per 64B slot-row

#pragma unroll
    for (int k = 0; k < 16; k++) {
        const int i = (ih << 4) + k;
        float4 wv = wq[k];                          // 1 wf (4-way oq dedup)
        ulonglong2 sA = sf2[i * 8 + oq * 2];        // 8 o fp32 = 32B
        ulonglong2 sB = sf2[i * 8 + oq * 2 + 1];

        unsigned su = __float_as_uint(wv.w);
        int   j   = (int)(su & 15u);
        float sil = __uint_as_float(su & ~15u);
        float w0 = wv.x, w2 = wv.y, w3 = wv.z;
        float w1 = 1.0f - w0 - w2 - w3;
        u64t w0p = pack2(w0, w0), w1p = pack2(w1, w1);
        u64t w2p = pack2(w2, w2), w3p = pack2(w3, w3);
        u64t slp = pack2(sil, sil);

        const uint4* tr = Tu + i * 72 + j * 4 + oq;
        uint4 t0 = tr[0];
        uint4 t1 = tr[4];
        uint4 t2 = tr[8];
        uint4 t3 = tr[12];

        fma2(acc01, slp, sA.x); fma2(acc23, slp, sA.y);
        fma2(acc45, slp, sB.x); fma2(acc67, slp, sB.y);

#define ROW2(T, W)                                 \
        fma2(acc01, W, bfpair(T.x));               \
        fma2(acc23, W, bfpair(T.y));               \
        fma2(acc45, W, bfpair(T.z));               \
        fma2(acc67, W, bfpair(T.w));

        ROW2(t0, w0p) ROW2(t1, w1p) ROW2(t2, w2p) ROW2(t3, w3p)
#undef ROW2
    }

    // ---- reduce across ih lanes (stride-4 butterfly on f32x2) ----
#pragma unroll
    for (int d = 4; d < 32; d <<= 1) {
        acc01 = add2(acc01, __shfl_xor_sync(0xffffffffu, acc01, d));
        acc23 = add2(acc23, __shfl_xor_sync(0xffffffffu, acc23, d));
        acc45 = add2(acc45, __shfl_xor_sync(0xffffffffu, acc45, d));
        acc67 = add2(acc67, __shfl_xor_sync(0xffffffffu, acc67, d));
    }

    if (ih == 0) {
        float2 a01 = unpack2(acc01), a23 = unpack2(acc23);
        float2 a45 = unpack2(acc45), a67 = unpack2(acc67);
        float4* op = (float4*)(out + (size_t)(b0 + warp) * OUT_DIM + obase + oq * 8);
        op[0] = make_float4(a01.x, a01.y, a23.x, a23.y);
        op[1] = make_float4(a45.x, a45.y, a67.x, a67.y);
    }
}

extern "C" void kernel_launch(void* const* d_in, const int* in_sizes, int n_in,
                              void* d_out, int out_size) {
    const float* x  = (const float*)d_in[0];  // (1024, 128)
    const float* cp = (const float*)d_in[1];  // (128, 128, 11)
    const float* sf = (const float*)d_in[2];  // (128, 128)
    // d_in[3] = grids: uniform, fixed -> hardcoded
    float* out = (float*)d_out;

    const int batch = in_sizes[0] / IN_DIM;

    cudaFuncSetAttribute(kan_fused, cudaFuncAttributeMaxDynamicSharedMemorySize, SMEM_TOT);

    dim3 grid((batch + TB - 1) / TB, OUT_DIM / OCH);   // 32 x 4 = 128 CTAs
    kan_fused<<<grid, NTH, SMEM_TOT>>>(x, cp, sf, out, batch);
}

// round 12
// speedup vs baseline: 1.1810x; 1.1810x over previous
#include <cuda_runtime.h>
#include <cuda_bf16.h>
#include <cstdint>

// Problem constants (fixed by reference)
#define IN_DIM   128
#define OUT_DIM  128
#define NCP      11
#define SSTR     20            // K slots per input dim i
#define ICH      16            // i's per K-split
#define KSPLIT   8
#define KC       (ICH * SSTR)  // 320 K per CTA
#define KSTRIDE  328           // padded row stride (halfwords); 656B, 16B-aligned, cf ldmatrix
#define MT       64            // batch rows per M-tile
#define NTH      1024
#define MAXB     1024
#define NMT      16            // max M-tiles

#define A_OFF    0
#define A_BYTES  (MT * KSTRIDE * 2)        // 41984
#define B_OFF    A_BYTES
#define B_BYTES  (OUT_DIM * KSTRIDE * 2)   // 83968
#define SMEM_TOT (A_OFF + A_BYTES + B_BYTES)

__device__ __align__(16) float g_part[KSPLIT][MAXB][OUT_DIM];
__device__ unsigned g_ctr[NMT];

__device__ __forceinline__ uint32_t smem_u32(const void* p) {
    uint32_t a;
    asm("{ .reg .u64 t; cvta.to.shared.u64 t, %1; cvt.u32.u64 %0, t; }" : "=r"(a) : "l"(p));
    return a;
}
__device__ __forceinline__ void ldsm_x4(uint32_t& r0, uint32_t& r1, uint32_t& r2,
                                        uint32_t& r3, uint32_t addr) {
    asm volatile("ldmatrix.sync.aligned.m8n8.x4.shared.b16 {%0,%1,%2,%3}, [%4];"
                 : "=r"(r0), "=r"(r1), "=r"(r2), "=r"(r3) : "r"(addr));
}
__device__ __forceinline__ void mma_bf16(float* c, uint32_t a0, uint32_t a1,
                                         uint32_t a2, uint32_t a3,
                                         uint32_t b0, uint32_t b1) {
    asm volatile("mma.sync.aligned.m16n8k16.row.col.f32.bf16.bf16.f32 "
                 "{%0,%1,%2,%3}, {%4,%5,%6,%7}, {%8,%9}, {%0,%1,%2,%3};"
                 : "+f"(c[0]), "+f"(c[1]), "+f"(c[2]), "+f"(c[3])
                 : "r"(a0), "r"(a1), "r"(a2), "r"(a3), "r"(b0), "r"(b1));
}

__global__ __launch_bounds__(NTH, 1)
void kan_mma(const float* __restrict__ x, const float* __restrict__ cp,
             const float* __restrict__ sf, float* __restrict__ out, int batch) {
    extern __shared__ char smem[];
    __nv_bfloat16* As = (__nv_bfloat16*)(smem + A_OFF);   // [64 b][328 k]
    __nv_bfloat16* Bs = (__nv_bfloat16*)(smem + B_OFF);   // [128 o][328 k]
    __shared__ unsigned s_old;

    const int tid = threadIdx.x;
    const int wid = tid >> 5, lane = tid & 31;
    const int mt = blockIdx.x, ks = blockIdx.y;
    const int b0 = mt * MT;
    const int i0 = ks * ICH;

    // ---- zero A (sparse; includes pad cols). B fully written below. ----
    {
        uint4 z = make_uint4(0u, 0u, 0u, 0u);
        uint4* az = (uint4*)(smem + A_OFF);
        for (int k = tid; k < A_BYTES / 16; k += NTH) az[k] = z;
    }

    // ---- build B: thread per (o, iL). slots 0..2,14..16=0; 3..13=sf*cp;
    //      17=sf_hi; 18=sf_lo; 19=sf_hi  (silu split-precision partner) ----
#pragma unroll
    for (int p = 0; p < 2; p++) {
        int s  = tid + p * NTH;          // 2048 = 128 o x 16 iL
        int o  = s >> 4;
        int iL = s & 15;
        const float* cprow = cp + ((size_t)(i0 + iL) * OUT_DIM + o) * NCP;
        float sv = sf[(size_t)(i0 + iL) * OUT_DIM + o];
        __nv_bfloat16 sh = __float2bfloat16(sv);
        float shf = __bfloat162float(sh);

        __nv_bfloat16* row = Bs + o * KSTRIDE + iL * SSTR;
        row[0] = row[1] = row[2] = __float2bfloat16(0.0f);
#pragma unroll
        for (int m = 0; m < NCP; m++) row[3 + m] = __float2bfloat16(sv * cprow[m]);
        row[14] = row[15] = row[16] = __float2bfloat16(0.0f);
        row[17] = sh;
        row[18] = __float2bfloat16(sv - shf);
        row[19] = sh;
    }
    __syncthreads();   // A zero done before sparse scatter

    // ---- build A: thread per (b, iL). 4 spline weights @ j..j+3, silu @ 17..19 ----
    {
        int b  = tid >> 4;
        int iL = tid & 15;
        float xv = (b0 + b < batch) ? x[(size_t)(b0 + b) * IN_DIM + (i0 + iL)] : 0.0f;
        float pos = (xv + 1.75f) * 4.0f;
        float fj  = floorf(pos);
        int   j   = (int)fj;
        float sil = xv / (1.0f + __expf(-xv));
        __nv_bfloat16 sih = __float2bfloat16(sil);

        __nv_bfloat16* row = As + b * KSTRIDE + iL * SSTR;
        row[17] = sih;                                        // * sf_hi
        row[18] = sih;                                        // * sf_lo
        row[19] = __float2bfloat16(sil - __bfloat162float(sih)); // lo * sf_hi
        if (j >= 0 && j <= 13) {
            float u = pos - fj, u2 = u * u, u3 = u2 * u, vv = 1.0f - u;
            const float c = 1.0f / 6.0f;
            row[j]     = __float2bfloat16(vv * vv * vv * c);
            row[j + 1] = __float2bfloat16((3.0f * u3 - 6.0f * u2 + 4.0f) * c);
            row[j + 2] = __float2bfloat16((-3.0f * u3 + 3.0f * u2 + 3.0f * u + 1.0f) * c);
            row[j + 3] = __float2bfloat16(u3 * c);
        }
    }
    __syncthreads();

    // ---- MMA mainloop: warp grid 4(m) x 8(n); warp tile 16m x 16n; 20 k-steps ----
    const int mw = wid >> 3;          // 0..3
    const int nw = wid & 7;           // 0..7
    const uint32_t sbA = smem_u32(As);
    const uint32_t sbB = smem_u32(Bs);
    // ldmatrix row addressing: lane&15 -> matrix row, lane>>4 -> 8-halfword k-half
    uint32_t aAddr = sbA + (uint32_t)(((mw * 16 + (lane & 15)) * KSTRIDE + (lane >> 4) * 8) * 2);
    uint32_t bAddr = sbB + (uint32_t)(((nw * 16 + (lane & 15)) * KSTRIDE + (lane >> 4) * 8) * 2);

    float c0[4] = {0.f, 0.f, 0.f, 0.f};   // n-frag 0 (cols nw*16 + 0..7)
    float c1[4] = {0.f, 0.f, 0.f, 0.f};   // n-frag 1 (cols nw*16 + 8..15)

#pragma unroll
    for (int k = 0; k < KC / 16; k++) {   // 20
        uint32_t a0, a1, a2, a3, r0, r1, r2, r3;
        ldsm_x4(a0, a1, a2, a3, aAddr + k * 32);
        ldsm_x4(r0, r1, r2, r3, bAddr + k * 32);
        // B frags: {k-low, k-high} per n8: nfrag0 = {r0, r2}, nfrag1 = {r1, r3}
        mma_bf16(c0, a0, a1, a2, a3, r0, r2);
        mma_bf16(c1, a0, a1, a2, a3, r1, r3);
    }

    // ---- epilogue: STG partial slab (c-frag: row = lane>>2 (+8), col = (lane&3)*2) ----
    {
        const int mrow = b0 + mw * 16 + (lane >> 2);
        const int ncol = nw * 16 + (lane & 3) * 2;
        float2* p0 = (float2*)(&g_part[ks][mrow][ncol]);
        float2* p1 = (float2*)(&g_part[ks][mrow + 8][ncol]);
        p0[0] = make_float2(c0[0], c0[1]);
        p1[0] = make_float2(c0[2], c0[3]);
        p0[4] = make_float2(c1[0], c1[1]);   // +8 cols = 4 float2
        p1[4] = make_float2(c1[2], c1[3]);
    }

    // ---- last K-split CTA of this M-tile reduces 8 slabs -> out ----
    __threadfence();
    __syncthreads();
    if (tid == 0) s_old = atomicAdd(&g_ctr[mt], 1u);
    __syncthreads();
    if ((s_old % KSPLIT) != (KSPLIT - 1)) return;
    __threadfence();

    const int n4 = MT * OUT_DIM / 4;                  // 2048 float4
    const int cstride = MAXB * OUT_DIM / 4;
    const float4* pbase = (const float4*)g_part + (size_t)b0 * (OUT_DIM / 4);
    for (int idx = tid; idx < n4; idx += NTH) {
        if (b0 + idx / (OUT_DIM / 4) >= batch) break;
        float4 a = pbase[idx];
#pragma unroll
        for (int c = 1; c < KSPLIT; c++) {
            float4 b = pbase[(size_t)c * cstride + idx];
            a.x += b.x; a.y += b.y; a.z += b.z; a.w += b.w;
        }
        ((float4*)(out + (size_t)b0 * OUT_DIM))[idx] = a;
    }
}

extern "C" void kernel_launch(void* const* d_in, const int* in_sizes, int n_in,
                              void* d_out, int out_size) {
    const float* x  = (const float*)d_in[0];  // (1024, 128)
    const float* cp = (const float*)d_in[1];  // (128, 128, 11)
    const float* sf = (const float*)d_in[2];  // (128, 128)
    // d_in[3] = grids: uniform, fixed -> hardcoded
    float* out = (float*)d_out;

    const int batch = in_sizes[0] / IN_DIM;

    cudaFuncSetAttribute(kan_mma, cudaFuncAttributeMaxDynamicSharedMemorySize, SMEM_TOT);

    dim3 grid((batch + MT - 1) / MT, KSPLIT);   // 16 x 8 = 128 CTAs
    kan_mma<<<grid, NTH, SMEM_TOT>>>(x, cp, sf, out, batch);
}

// round 13
// speedup vs baseline: 1.4608x; 1.2369x over previous
#include <cuda_runtime.h>
#include <cuda_bf16.h>
#include <cstdint>

// Problem constants (fixed by reference)
#define IN_DIM   128
#define OUT_DIM  128
#define NCP      11
#define SSTR     20            // K slots per input dim i
#define ICH      16            // i's per K-split
#define KSPLIT   8
#define KC       (ICH * SSTR)  // 320 K per CTA
#define KSTRIDE  328           // padded row stride (halfwords); 656B, 16B-aligned rows
#define MT       64            // batch rows per M-tile
#define NTH      1024
#define MAXB     1024
#define NMT      16

#define A_OFF    0
#define A_BYTES  (MT * KSTRIDE * 2)        // 41984
#define B_OFF    A_BYTES
#define B_BYTES  (OUT_DIM * KSTRIDE * 2)   // 83968
#define CPS_OFF  (A_BYTES + B_BYTES)       // 125952 (cp staging: 8i x 128o x 11 fp32)
#define CPS_FLTS (8 * OUT_DIM * NCP)       // 11264
#define SMEM_TOT (CPS_OFF + CPS_FLTS * 4)  // 171008

__device__ __align__(16) float g_part[KSPLIT][MAXB][OUT_DIM];
__device__ unsigned g_ctr[NMT];

__device__ __forceinline__ uint32_t smem_u32(const void* p) {
    uint32_t a;
    asm("{ .reg .u64 t; cvta.to.shared.u64 t, %1; cvt.u32.u64 %0, t; }" : "=r"(a) : "l"(p));
    return a;
}
__device__ __forceinline__ void ldsm_x4(uint32_t& r0, uint32_t& r1, uint32_t& r2,
                                        uint32_t& r3, uint32_t addr) {
    asm volatile("ldmatrix.sync.aligned.m8n8.x4.shared.b16 {%0,%1,%2,%3}, [%4];"
                 : "=r"(r0), "=r"(r1), "=r"(r2), "=r"(r3) : "r"(addr));
}
__device__ __forceinline__ void mma_bf16(float* c, uint32_t a0, uint32_t a1,
                                         uint32_t a2, uint32_t a3,
                                         uint32_t b0, uint32_t b1) {
    asm volatile("mma.sync.aligned.m16n8k16.row.col.f32.bf16.bf16.f32 "
                 "{%0,%1,%2,%3}, {%4,%5,%6,%7}, {%8,%9}, {%0,%1,%2,%3};"
                 : "+f"(c[0]), "+f"(c[1]), "+f"(c[2]), "+f"(c[3])
                 : "r"(a0), "r"(a1), "r"(a2), "r"(a3), "r"(b0), "r"(b1));
}
__device__ __forceinline__ uint32_t packbf(float lo, float hi) {
    return (uint32_t)__bfloat16_as_ushort(__float2bfloat16(lo))
         | ((uint32_t)__bfloat16_as_ushort(__float2bfloat16(hi)) << 16);
}

__global__ __launch_bounds__(NTH, 1)
void kan_mma(const float* __restrict__ x, const float* __restrict__ cp,
             const float* __restrict__ sf, float* __restrict__ out, int batch) {
    extern __shared__ char smem[];
    __nv_bfloat16* As  = (__nv_bfloat16*)(smem + A_OFF);   // [64 b][328 k]
    __nv_bfloat16* Bs  = (__nv_bfloat16*)(smem + B_OFF);   // [128 o][328 k]
    float*         cps = (float*)(smem + CPS_OFF);         // [8 i][128 o][11]
    __shared__ unsigned s_old;

    const int tid = threadIdx.x;
    const int wid = tid >> 5, lane = tid & 31;
    const int mt = blockIdx.x, ks = blockIdx.y;
    const int b0 = mt * MT;
    const int i0 = ks * ICH;

    // ---- issue half-0 staging loads early (coalesced; cp chunk is contiguous) ----
    const float4* cp4 = (const float4*)(cp + (size_t)i0 * OUT_DIM * NCP);
    float4 st[3];
#pragma unroll
    for (int k = 0; k < 3; k++) {
        int idx = tid + k * NTH;
        st[k] = (idx < CPS_FLTS / 4) ? cp4[idx] : make_float4(0.f, 0.f, 0.f, 0.f);
    }

    // ---- build A while staging loads are in flight: full 20-slot rows (no zero phase) ----
    {
        int b  = tid >> 4;          // 0..63
        int iL = tid & 15;
        float xv = (b0 + b < batch) ? x[(size_t)(b0 + b) * IN_DIM + (i0 + iL)] : 0.0f;
        float pos = (xv + 1.75f) * 4.0f;
        float fj  = floorf(pos);
        int   j   = (int)fj;
        float sil = xv / (1.0f + __expf(-xv));
        __nv_bfloat16 sih = __float2bfloat16(sil);

        float vals[SSTR];
#pragma unroll
        for (int m = 0; m < SSTR; m++) vals[m] = 0.0f;
        if (j >= 0 && j <= 13) {
            float u = pos - fj, u2 = u * u, u3 = u2 * u, vv = 1.0f - u;
            const float c = 1.0f / 6.0f;
            vals[j]     = vv * vv * vv * c;
            vals[j + 1] = (3.0f * u3 - 6.0f * u2 + 4.0f) * c;
            vals[j + 2] = (-3.0f * u3 + 3.0f * u2 + 3.0f * u + 1.0f) * c;
            vals[j + 3] = u3 * c;
        }
        vals[17] = __bfloat162float(sih);
        vals[18] = vals[17];
        vals[19] = sil - vals[17];

        uint32_t* row = (uint32_t*)(As + b * KSTRIDE + iL * SSTR);  // 4B-aligned
#pragma unroll
        for (int p = 0; p < SSTR / 2; p++)
            row[p] = packbf(vals[2 * p], vals[2 * p + 1]);
    }

    // ---- two halves: stage cp -> smem, then conflict-free gather-build B ----
#pragma unroll 1
    for (int half = 0; half < 2; half++) {
        // store staged registers
#pragma unroll
        for (int k = 0; k < 3; k++) {
            int idx = tid + k * NTH;
            if (idx < CPS_FLTS / 4) ((float4*)cps)[idx] = st[k];
        }
        // prefetch next half while this half is consumed
        if (half == 0) {
#pragma unroll
            for (int k = 0; k < 3; k++) {
                int idx = tid + k * NTH;
                st[k] = (idx < CPS_FLTS / 4) ? cp4[CPS_FLTS / 4 + idx]
                                             : make_float4(0.f, 0.f, 0.f, 0.f);
            }
        }
        __syncthreads();

        // build B rows for 8 i's x 128 o: LDS stride 11 words (gcd(11,32)=1, cf)
        {
            int o   = tid & 127;
            int iL8 = tid >> 7;            // 0..7
            int iL  = half * 8 + iL8;
            const float* src = cps + (iL8 * OUT_DIM + o) * NCP;
            float sv = sf[(size_t)(i0 + iL) * OUT_DIM + o];   // coalesced LDG
            __nv_bfloat16 sh = __float2bfloat16(sv);
            float shf = __bfloat162float(sh);

            float vals[SSTR];
            vals[0] = vals[1] = vals[2] = 0.0f;
#pragma unroll
            for (int m = 0; m < NCP; m++) vals[3 + m] = sv * src[m];
            vals[14] = vals[15] = vals[16] = 0.0f;
            vals[17] = shf;
            vals[18] = sv - shf;
            vals[19] = shf;

            uint32_t* row = (uint32_t*)(Bs + o * KSTRIDE + iL * SSTR);
#pragma unroll
            for (int p = 0; p < SSTR / 2; p++)
                row[p] = packbf(vals[2 * p], vals[2 * p + 1]);
        }
        __syncthreads();
    }

    // ---- MMA mainloop: warp grid 4(m) x 8(n); warp tile 16m x 16n; 20 k-steps ----
    const int mw = wid >> 3;
    const int nw = wid & 7;
    const uint32_t sbA = smem_u32(As);
    const uint32_t sbB = smem_u32(Bs);
    uint32_t aAddr = sbA + (uint32_t)(((mw * 16 + (lane & 15)) * KSTRIDE + (lane >> 4) * 8) * 2);
    uint32_t bAddr = sbB + (uint32_t)(((nw * 16 + (lane & 15)) * KSTRIDE + (lane >> 4) * 8) * 2);

    float c0[4] = {0.f, 0.f, 0.f, 0.f};
    float c1[4] = {0.f, 0.f, 0.f, 0.f};

#pragma unroll
    for (int k = 0; k < KC / 16; k++) {   // 20
        uint32_t a0, a1, a2, a3, r0, r1, r2, r3;
        ldsm_x4(a0, a1, a2, a3, aAddr + k * 32);
        ldsm_x4(r0, r1, r2, r3, bAddr + k * 32);
        mma_bf16(c0, a0, a1, a2, a3, r0, r2);
        mma_bf16(c1, a0, a1, a2, a3, r1, r3);
    }

    // ---- epilogue: STG partial slab ----
    {
        const int mrow = b0 + mw * 16 + (lane >> 2);
        const int ncol = nw * 16 + (lane & 3) * 2;
        float2* p0 = (float2*)(&g_part[ks][mrow][ncol]);
        float2* p1 = (float2*)(&g_part[ks][mrow + 8][ncol]);
        p0[0] = make_float2(c0[0], c0[1]);
        p1[0] = make_float2(c0[2], c0[3]);
        p0[4] = make_float2(c1[0], c1[1]);
        p1[4] = make_float2(c1[2], c1[3]);
    }

    // ---- last K-split CTA of this M-tile reduces 8 slabs -> out ----
    __threadfence();
    __syncthreads();
    if (tid == 0) s_old = atomicAdd(&g_ctr[mt], 1u);
    __syncthreads();
    if ((s_old % KSPLIT) != (KSPLIT - 1)) return;
    __threadfence();

    const int n4 = MT * OUT_DIM / 4;
    const int cstride = MAXB * OUT_DIM / 4;
    const float4* pbase = (const float4*)g_part + (size_t)b0 * (OUT_DIM / 4);
    for (int idx = tid; idx < n4; idx += NTH) {
        if (b0 + idx / (OUT_DIM / 4) >= batch) break;
        float4 a = pbase[idx];
#pragma unroll
        for (int c = 1; c < KSPLIT; c++) {
            float4 b = pbase[(size_t)c * cstride + idx];
            a.x += b.x; a.y += b.y; a.z += b.z; a.w += b.w;
        }
        ((float4*)(out + (size_t)b0 * OUT_DIM))[idx] = a;
    }
}

extern "C" void kernel_launch(void* const* d_in, const int* in_sizes, int n_in,
                              void* d_out, int out_size) {
    const float* x  = (const float*)d_in[0];  // (1024, 128)
    const float* cp = (const float*)d_in[1];  // (128, 128, 11)
    const float* sf = (const float*)d_in[2];  // (128, 128)
    // d_in[3] = grids: uniform, fixed -> hardcoded
    float* out = (float*)d_out;

    const int batch = in_sizes[0] / IN_DIM;

    cudaFuncSetAttribute(kan_mma, cudaFuncAttributeMaxDynamicSharedMemorySize, SMEM_TOT);

    dim3 grid((batch + MT - 1) / MT, KSPLIT);   // 16 x 8 = 128 CTAs
    kan_mma<<<grid, NTH, SMEM_TOT>>>(x, cp, sf, out, batch);
}

// round 14
// speedup vs baseline: 1.6589x; 1.1356x over previous
#include <cuda_runtime.h>
#include <cuda_bf16.h>
#include <cstdint>

// Problem constants (fixed by reference)
#define IN_DIM   128
#define OUT_DIM  128
#define NCP      11
#define SSTR     20            // K slots per input dim i
#define ICH      16            // i's per K-split
#define KSPLIT   8
#define KC       (ICH * SSTR)  // 320 K per CTA
#define KSTRIDE  328           // padded row stride (halfwords); 656B
#define MT       64            // batch rows per M-tile
#define NTH      1024
#define MAXB     1024
#define NMT      16

#define A_OFF    0
#define A_BYTES  (MT * KSTRIDE * 2)        // 41984
#define B_OFF    A_BYTES
#define B_BYTES  (OUT_DIM * KSTRIDE * 2)   // 83968
#define CPS_OFF  (A_BYTES + B_BYTES)       // 125952
#define CPS_FLTS (ICH * OUT_DIM * NCP)     // 22528 (full chunk)
#define SMEM_TOT (CPS_OFF + CPS_FLTS * 4)  // 216064

__device__ __align__(16) float g_part[KSPLIT][MAXB][OUT_DIM];
__device__ unsigned g_ctr[NMT];

__device__ __forceinline__ uint32_t smem_u32(const void* p) {
    uint32_t a;
    asm("{ .reg .u64 t; cvta.to.shared.u64 t, %1; cvt.u32.u64 %0, t; }" : "=r"(a) : "l"(p));
    return a;
}
__device__ __forceinline__ void ldsm_x4(uint32_t& r0, uint32_t& r1, uint32_t& r2,
                                        uint32_t& r3, uint32_t addr) {
    asm volatile("ldmatrix.sync.aligned.m8n8.x4.shared.b16 {%0,%1,%2,%3}, [%4];"
                 : "=r"(r0), "=r"(r1), "=r"(r2), "=r"(r3) : "r"(addr));
}
__device__ __forceinline__ void mma_bf16(float* c, uint32_t a0, uint32_t a1,
                                         uint32_t a2, uint32_t a3,
                                         uint32_t b0, uint32_t b1) {
    asm volatile("mma.sync.aligned.m16n8k16.row.col.f32.bf16.bf16.f32 "
                 "{%0,%1,%2,%3}, {%4,%5,%6,%7}, {%8,%9}, {%0,%1,%2,%3};"
                 : "+f"(c[0]), "+f"(c[1]), "+f"(c[2]), "+f"(c[3])
                 : "r"(a0), "r"(a1), "r"(a2), "r"(a3), "r"(b0), "r"(b1));
}
__device__ __forceinline__ uint32_t packbf(float lo, float hi) {
    return (uint32_t)__bfloat16_as_ushort(__float2bfloat16(lo))
         | ((uint32_t)__bfloat16_as_ushort(__float2bfloat16(hi)) << 16);
}
__device__ __forceinline__ unsigned ld_acq(const unsigned* p) {
    unsigned v;
    asm volatile("ld.acquire.gpu.global.u32 %0, [%1];" : "=r"(v) : "l"(p) : "memory");
    return v;
}

__global__ __launch_bounds__(NTH, 1)
void kan_mma(const float* __restrict__ x, const float* __restrict__ cp,
             const float* __restrict__ sf, float* __restrict__ out, int batch) {
    extern __shared__ char smem[];
    __nv_bfloat16* As  = (__nv_bfloat16*)(smem + A_OFF);   // [64 b][328 k]
    __nv_bfloat16* Bs  = (__nv_bfloat16*)(smem + B_OFF);   // [128 o][328 k]
    float*         cps = (float*)(smem + CPS_OFF);         // [16 i][128 o][11]
    __shared__ unsigned s_tgt;

    const int tid = threadIdx.x;
    const int wid = tid >> 5, lane = tid & 31;
    const int mt = blockIdx.x, ks = blockIdx.y;
    const int b0 = mt * MT;
    const int i0 = ks * ICH;

    // ---- phase 0: ALL gmem loads issue up front (high MLP), A built inline ----
    const int oB   = tid & 127;        // B-build o for both halves
    const int iL8  = tid >> 7;         // 0..7
    float sv0 = sf[(size_t)(i0 + iL8) * OUT_DIM + oB];          // half 0
    float sv1 = sf[(size_t)(i0 + 8 + iL8) * OUT_DIM + oB];      // half 1

    // cp staging: 5632 float4, 6 per thread, coalesced copy gmem->smem
    {
        const float4* cp4 = (const float4*)(cp + (size_t)i0 * OUT_DIM * NCP);
        float4* cd = (float4*)cps;
#pragma unroll
        for (int k = 0; k < 6; k++) {
            int idx = tid + k * NTH;
            if (idx < CPS_FLTS / 4) cd[idx] = cp4[idx];
        }
    }

    // A build: thread per (b, iL), full 20-slot row
    {
        int b  = tid >> 4;          // 0..63
        int iL = tid & 15;
        float xv = (b0 + b < batch) ? x[(size_t)(b0 + b) * IN_DIM + (i0 + iL)] : 0.0f;
        float pos = (xv + 1.75f) * 4.0f;
        float fj  = floorf(pos);
        int   j   = (int)fj;
        float sil = xv / (1.0f + __expf(-xv));
        float sih = __bfloat162float(__float2bfloat16(sil));

        float vals[SSTR];
#pragma unroll
        for (int m = 0; m < SSTR; m++) vals[m] = 0.0f;
        if (j >= 0 && j <= 13) {
            float u = pos - fj, u2 = u * u, u3 = u2 * u, vv = 1.0f - u;
            const float c = 1.0f / 6.0f;
            vals[j]     = vv * vv * vv * c;
            vals[j + 1] = (3.0f * u3 - 6.0f * u2 + 4.0f) * c;
            vals[j + 2] = (-3.0f * u3 + 3.0f * u2 + 3.0f * u + 1.0f) * c;
            vals[j + 3] = u3 * c;
        }
        vals[17] = sih;
        vals[18] = sih;
        vals[19] = sil - sih;

        uint32_t* row = (uint32_t*)(As + b * KSTRIDE + iL * SSTR);
#pragma unroll
        for (int p = 0; p < SSTR / 2; p++)
            row[p] = packbf(vals[2 * p], vals[2 * p + 1]);
    }
    __syncthreads();

    // ---- phase 1: build B (both halves; LDS stride 11 words: conflict-free) ----
#pragma unroll
    for (int h = 0; h < 2; h++) {
        int iL = h * 8 + iL8;
        float sv = h ? sv1 : sv0;
        const float* src = cps + ((size_t)iL * OUT_DIM + oB) * NCP;
        float shf = __bfloat162float(__float2bfloat16(sv));

        float vals[SSTR];
        vals[0] = vals[1] = vals[2] = 0.0f;
#pragma unroll
        for (int m = 0; m < NCP; m++) vals[3 + m] = sv * src[m];
        vals[14] = vals[15] = vals[16] = 0.0f;
        vals[17] = shf;
        vals[18] = sv - shf;
        vals[19] = shf;

        uint32_t* row = (uint32_t*)(Bs + oB * KSTRIDE + iL * SSTR);
#pragma unroll
        for (int p = 0; p < SSTR / 2; p++)
            row[p] = packbf(vals[2 * p], vals[2 * p + 1]);
    }
    __syncthreads();

    // ---- phase 2: MMA. warp grid 4(m) x 8(n); warp tile 16m x 16n; 20 k-steps ----
    const int mw = wid >> 3;
    const int nw = wid & 7;
    uint32_t aAddr = smem_u32(As)
        + (uint32_t)(((mw * 16 + (lane & 15)) * KSTRIDE + (lane >> 4) * 8) * 2);
    uint32_t bAddr = smem_u32(Bs)
        + (uint32_t)(((nw * 16 + (lane & 15)) * KSTRIDE + (lane >> 4) * 8) * 2);

    float c0[4] = {0.f, 0.f, 0.f, 0.f};
    float c1[4] = {0.f, 0.f, 0.f, 0.f};
#pragma unroll
    for (int k = 0; k < KC / 16; k++) {   // 20
        uint32_t a0, a1, a2, a3, r0, r1, r2, r3;
        ldsm_x4(a0, a1, a2, a3, aAddr + k * 32);
        ldsm_x4(r0, r1, r2, r3, bAddr + k * 32);
        mma_bf16(c0, a0, a1, a2, a3, r0, r2);
        mma_bf16(c1, a0, a1, a2, a3, r1, r3);
    }

    // epilogue: STG partial slab
    {
        const int mrow = b0 + mw * 16 + (lane >> 2);
        const int ncol = nw * 16 + (lane & 3) * 2;
        float2* p0 = (float2*)(&g_part[ks][mrow][ncol]);
        float2* p1 = (float2*)(&g_part[ks][mrow + 8][ncol]);
        p0[0] = make_float2(c0[0], c0[1]);
        p1[0] = make_float2(c0[2], c0[3]);
        p0[4] = make_float2(c1[0], c1[1]);
        p1[4] = make_float2(c1[2], c1[3]);
    }

    // ---- phase 3: all-CTA distributed reduce (spin-free-ish barrier) ----
    // Safe: grid = 128 CTAs <= 148 SMs, 1 CTA/SM -> whole grid co-resident.
    __threadfence();                       // release partial stores
    __syncthreads();
    if (tid == 0) {
        unsigned old = atomicAdd(&g_ctr[mt], 1u);
        unsigned tgt = old - (old % KSPLIT) + KSPLIT;   // end of this replay's epoch
        while (ld_acq(&g_ctr[mt]) < tgt) __nanosleep(64);
        s_tgt = 1u;
    }
    __syncthreads();                       // all threads: column complete

    // each CTA reduces its 1/8 share: 1 float/thread, 8 coalesced LDG, MLP=8
    {
        int f   = ks * NTH + tid;          // 0..8191 within this M-tile
        int row = b0 + (f >> 7);
        int col = f & 127;
        if (row < batch) {
            const float* pb = &g_part[0][row][col];
            float a = 0.0f;
#pragma unroll
            for (int c = 0; c < KSPLIT; c++)
                a += pb[(size_t)c * (MAXB * OUT_DIM)];
            out[(size_t)row * OUT_DIM + col] = a;
        }
    }
}

extern "C" void kernel_launch(void* const* d_in, const int* in_sizes, int n_in,
                              void* d_out, int out_size) {
    const float* x  = (const float*)d_in[0];  // (1024, 128)
    const float* cp = (const float*)d_in[1];  // (128, 128, 11)
    const float* sf = (const float*)d_in[2];  // (128, 128)
    // d_in[3] = grids: uniform, fixed -> hardcoded
    float* out = (float*)d_out;

    const int batch = in_sizes[0] / IN_DIM;

    cudaFuncSetAttribute(kan_mma, cudaFuncAttributeMaxDynamicSharedMemorySize, SMEM_TOT);

    dim3 grid((batch + MT - 1) / MT, KSPLIT);   // 16 x 8 = 128 CTAs
    kan_mma<<<grid, NTH, SMEM_TOT>>>(x, cp, sf, out, batch);
}